// round 2
// baseline (speedup 1.0000x reference)
#include <cuda_runtime.h>
#include <cuda_bf16.h>
#include <math_constants.h>

// ---------------------------------------------------------------------------
// WindowAttention: x(512,65,1024), x_(512,129,1024) -> out(512,65,1024)
// H=16 heads, D=64, WIN=64, REC=128, nW (device scalar, =64)
// Pipeline: Q = x@Wq+bq ; KV = x_@Wkv+bkv ; fused attention w/ rel-pos bias,
// cls biases, boundary masks, softmax ; out = AO@Wp+bp
// Masks arrive as int32 (bool inputs are promoted by the harness).
// ---------------------------------------------------------------------------

#define NTOK 65
#define MTOK 129
#define NHEAD 16
#define HDIM 64
#define CDIM 1024

// scratch (allocation-free: __device__ globals)
__device__ float g_q [512 * NTOK * CDIM];        // 136 MB
__device__ float g_kv[512 * MTOK * 2 * CDIM];    // 541 MB
__device__ float g_ao[512 * NTOK * CDIM];        // 136 MB

// ---------------------------------------------------------------------------
// fp32 tiled GEMM: C[M,N] = A[M,K] @ B[K,N] + bias[N]
// BM=BN=128, BK=8, 256 threads, 8x8 per thread. All dims divide exactly.
// ---------------------------------------------------------------------------
#define BM 128
#define BN 128
#define BK 8
#define TM 8
#define TN 8

__global__ __launch_bounds__(256) void sgemm_bias(
    const float* __restrict__ A, const float* __restrict__ B,
    const float* __restrict__ bias, float* __restrict__ C,
    int M, int N, int K)
{
    __shared__ float As[BK][BM];
    __shared__ float Bs[BK][BN];

    const int tid = threadIdx.x;
    const int bx = blockIdx.x;   // N tile
    const int by = blockIdx.y;   // M tile
    const int tx = tid & 15;     // 0..15
    const int ty = tid >> 4;     // 0..15

    const float* Ab = A + (size_t)by * BM * K;
    const float* Bb = B + (size_t)bx * BN;

    const int arow = tid >> 1;          // 0..127
    const int acol = (tid & 1) * 4;     // 0 or 4
    const int brow = tid >> 5;          // 0..7
    const int bcol = (tid & 31) * 4;    // 0..124

    float acc[TM][TN];
    #pragma unroll
    for (int i = 0; i < TM; i++)
        #pragma unroll
        for (int j = 0; j < TN; j++) acc[i][j] = 0.f;

    for (int k0 = 0; k0 < K; k0 += BK) {
        float4 av = *(const float4*)(Ab + (size_t)arow * K + k0 + acol);
        As[acol + 0][arow] = av.x;
        As[acol + 1][arow] = av.y;
        As[acol + 2][arow] = av.z;
        As[acol + 3][arow] = av.w;
        *(float4*)(&Bs[brow][bcol]) =
            *(const float4*)(Bb + (size_t)(k0 + brow) * N + bcol);
        __syncthreads();

        #pragma unroll
        for (int k = 0; k < BK; k++) {
            float a[TM], b[TN];
            float4 a0 = *(const float4*)(&As[k][ty * TM]);
            float4 a1 = *(const float4*)(&As[k][ty * TM + 4]);
            a[0]=a0.x; a[1]=a0.y; a[2]=a0.z; a[3]=a0.w;
            a[4]=a1.x; a[5]=a1.y; a[6]=a1.z; a[7]=a1.w;
            float4 b0 = *(const float4*)(&Bs[k][tx * TN]);
            float4 b1 = *(const float4*)(&Bs[k][tx * TN + 4]);
            b[0]=b0.x; b[1]=b0.y; b[2]=b0.z; b[3]=b0.w;
            b[4]=b1.x; b[5]=b1.y; b[6]=b1.z; b[7]=b1.w;
            #pragma unroll
            for (int i = 0; i < TM; i++)
                #pragma unroll
                for (int j = 0; j < TN; j++)
                    acc[i][j] = fmaf(a[i], b[j], acc[i][j]);
        }
        __syncthreads();
    }

    const float* brow_bias = bias + (size_t)bx * BN + tx * TN;
    float bv[TN];
    #pragma unroll
    for (int j = 0; j < TN; j++) bv[j] = brow_bias[j];

    #pragma unroll
    for (int i = 0; i < TM; i++) {
        size_t r = (size_t)by * BM + ty * TM + i;
        float* Crow = C + r * N + (size_t)bx * BN + tx * TN;
        float4 o0, o1;
        o0.x = acc[i][0] + bv[0]; o0.y = acc[i][1] + bv[1];
        o0.z = acc[i][2] + bv[2]; o0.w = acc[i][3] + bv[3];
        o1.x = acc[i][4] + bv[4]; o1.y = acc[i][5] + bv[5];
        o1.z = acc[i][6] + bv[6]; o1.w = acc[i][7] + bv[7];
        *(float4*)(Crow)     = o0;
        *(float4*)(Crow + 4) = o1;
    }
}

// ---------------------------------------------------------------------------
// Fused attention: one block per (head, window). 256 threads = 8 warps.
// Each warp owns query rows n = warp, warp+8, ...
// ---------------------------------------------------------------------------
#define KSTRIDE 65   // padded row stride for K/V in smem (bank-conflict-free)

__global__ __launch_bounds__(256) void attn_kernel(
    const float* __restrict__ q, const float* __restrict__ kv,
    const int* __restrict__ mask_l,
    const int* __restrict__ mask_r,
    const int* __restrict__ nW_ptr,
    const float* __restrict__ rel_table,
    const float* __restrict__ cls_self,
    const float* __restrict__ cls_up,
    const float* __restrict__ cls_down,
    float* __restrict__ ao)
{
    const int h = blockIdx.x;
    const int b = blockIdx.y;
    const int tid = threadIdx.x;
    const int lane = tid & 31;
    const int warp = tid >> 5;

    extern __shared__ float sm[];
    float* Ks = sm;                         // [129][65]
    float* Vs = Ks + MTOK * KSTRIDE;        // [129][65]
    float* Qs = Vs + MTOK * KSTRIDE;        // [65][64]
    float* Ps = Qs + NTOK * HDIM;           // [8][132]

    const int nW = *nW_ptr;
    const int mc = (nW < 2) ? nW : 2;
    const int w = b % nW;
    const bool use_l = (w < mc);
    const bool use_r = (w >= nW - mc);
    const int* ml = mask_l + (size_t)w * NTOK * MTOK;
    const int* mr = mask_r +
        (size_t)(2 - mc + (w - (nW - mc))) * NTOK * MTOK;

    // stage K, V (head slice) into smem
    const float* kvb = kv + (size_t)b * MTOK * 2 * CDIM + h * HDIM;
    for (int idx = tid; idx < MTOK * HDIM; idx += 256) {
        int m = idx >> 6, d = idx & 63;
        Ks[m * KSTRIDE + d] = kvb[(size_t)m * 2048 + d];
        Vs[m * KSTRIDE + d] = kvb[(size_t)m * 2048 + CDIM + d];
    }
    // stage Q (head slice)
    const float* qb = q + (size_t)b * NTOK * CDIM + h * HDIM;
    for (int idx = tid; idx < NTOK * HDIM; idx += 256) {
        int n = idx >> 6, d = idx & 63;
        Qs[idx] = qb[(size_t)n * CDIM + d];
    }
    __syncthreads();

    const float scale = 0.125f;     // 64^-0.5
    const float NEG = -3.402823466e38f;

    for (int n = warp; n < NTOK; n += 8) {
        const int nm = (lane == 0) ? 5 : 4;   // m=128 handled by lane 0
        float s[5];

        for (int j = 0; j < nm; j++) {
            const int m = lane + 32 * j;
            const float* kr = Ks + m * KSTRIDE;
            const float* qr = Qs + n * HDIM;
            float acc = 0.f;
            #pragma unroll
            for (int d = 0; d < HDIM; d++) acc = fmaf(qr[d], kr[d], acc);
            acc *= scale;

            // bias: [cls_self | cls_up ; cls_down | rel]
            float bias;
            if (n == 0)
                bias = (m == 0) ? cls_self[h] : cls_up[h * (MTOK - 1) + (m - 1)];
            else
                bias = (m == 0) ? cls_down[h * (NTOK - 1) + (n - 1)]
                                : rel_table[(n - m + 127) * NHEAD + h];
            acc += bias;

            bool masked = false;
            if (use_l) masked = ml[n * MTOK + m] != 0;
            if (use_r) masked = masked || (mr[n * MTOK + m] != 0);
            s[j] = masked ? NEG : acc;
        }

        // warp softmax across distributed m
        float mx = s[0];
        for (int j = 1; j < nm; j++) mx = fmaxf(mx, s[j]);
        #pragma unroll
        for (int o = 16; o; o >>= 1) mx = fmaxf(mx, __shfl_xor_sync(0xffffffffu, mx, o));
        float sum = 0.f, p[5];
        for (int j = 0; j < nm; j++) { p[j] = __expf(s[j] - mx); sum += p[j]; }
        #pragma unroll
        for (int o = 16; o; o >>= 1) sum += __shfl_xor_sync(0xffffffffu, sum, o);
        const float inv = 1.f / sum;

        float* Prow = Ps + warp * 132;
        for (int j = 0; j < nm; j++) Prow[lane + 32 * j] = p[j] * inv;
        __syncwarp();

        // out[n][d] = sum_m P[m] * V[m][d], d split lane / lane+32
        float o0 = 0.f, o1 = 0.f;
        for (int m = 0; m < MTOK; m++) {
            const float pm = Prow[m];
            o0 = fmaf(pm, Vs[m * KSTRIDE + lane], o0);
            o1 = fmaf(pm, Vs[m * KSTRIDE + lane + 32], o1);
        }
        float* aor = ao + ((size_t)b * NTOK + n) * CDIM + h * HDIM;
        aor[lane]      = o0;
        aor[lane + 32] = o1;
        __syncwarp();   // Ps reused next iteration
    }
}

// ---------------------------------------------------------------------------
// host launch
// ---------------------------------------------------------------------------
extern "C" void kernel_launch(void* const* d_in, const int* in_sizes, int n_in,
                              void* d_out, int out_size)
{
    const float* x        = (const float*)d_in[0];
    const float* x_       = (const float*)d_in[1];
    const int*   mask_l   = (const int*)d_in[2];
    const int*   mask_r   = (const int*)d_in[3];
    const int*   nW_ptr   = (const int*)d_in[4];
    const float* Wq       = (const float*)d_in[5];
    const float* bq       = (const float*)d_in[6];
    const float* Wkv      = (const float*)d_in[7];
    const float* bkv      = (const float*)d_in[8];
    const float* Wp       = (const float*)d_in[9];
    const float* bp       = (const float*)d_in[10];
    const float* rel      = (const float*)d_in[11];
    const float* cls_self = (const float*)d_in[12];
    const float* cls_up   = (const float*)d_in[13];
    const float* cls_down = (const float*)d_in[14];

    const int BnW = in_sizes[0] / (NTOK * CDIM);   // 512
    const int Mq  = BnW * NTOK;                    // 33280
    const int Mkv = BnW * MTOK;                    // 66048

    float *qbuf, *kvbuf, *aobuf;
    cudaGetSymbolAddress((void**)&qbuf,  g_q);
    cudaGetSymbolAddress((void**)&kvbuf, g_kv);
    cudaGetSymbolAddress((void**)&aobuf, g_ao);

    // Q projection: (BnW*65, 1024) = x @ Wq + bq
    sgemm_bias<<<dim3(CDIM / BN, Mq / BM), 256>>>(x, Wq, bq, qbuf, Mq, CDIM, CDIM);
    // KV projection: (BnW*129, 2048) = x_ @ Wkv + bkv
    sgemm_bias<<<dim3(2 * CDIM / BN, Mkv / BM), 256>>>(x_, Wkv, bkv, kvbuf, Mkv, 2 * CDIM, CDIM);

    // fused attention
    const int smem_bytes = (MTOK * KSTRIDE * 2 + NTOK * HDIM + 8 * 132) * sizeof(float);
    cudaFuncSetAttribute(attn_kernel, cudaFuncAttributeMaxDynamicSharedMemorySize, smem_bytes);
    attn_kernel<<<dim3(NHEAD, BnW), 256, smem_bytes>>>(
        qbuf, kvbuf, mask_l, mask_r, nW_ptr, rel, cls_self, cls_up, cls_down, aobuf);

    // output projection: (BnW*65, 1024) = ao @ Wp + bp
    sgemm_bias<<<dim3(CDIM / BN, Mq / BM), 256>>>(aobuf, Wp, bp, (float*)d_out, Mq, CDIM, CDIM);
}

// round 3
// speedup vs baseline: 2.3390x; 2.3390x over previous
#include <cuda_runtime.h>
#include <cuda_bf16.h>
#include <math_constants.h>

// ---------------------------------------------------------------------------
// WindowAttention: x(512,65,1024), x_(512,129,1024) -> out(512,65,1024)
// GEMMs on tensor cores (mma.sync tf32), fused attention in fp32 SIMT.
// ---------------------------------------------------------------------------

#define NTOK 65
#define MTOK 129
#define NHEAD 16
#define HDIM 64
#define CDIM 1024

__device__ float g_q [512 * NTOK * CDIM];
__device__ float g_kv[512 * MTOK * 2 * CDIM];
__device__ float g_ao[512 * NTOK * CDIM];

__device__ __forceinline__ unsigned f2tf32(float x) {
    unsigned r;
    asm("cvt.rna.tf32.f32 %0, %1;" : "=r"(r) : "f"(x));
    return r;
}

// ---------------------------------------------------------------------------
// tf32 tensor-core GEMM: C[M,N] = A[M,K] @ B[K,N] + bias[N]
// 128x128x32 block tile, 256 threads = 8 warps (2M x 4N), warp tile 64x32.
// mma.sync.aligned.m16n8k8.row.col.f32.tf32.tf32.f32
// Smem: A stride 36 words (bank = 4g+t, conflict-free),
//       B stride 136 words (bank = 8t+g, conflict-free).
// ---------------------------------------------------------------------------
#define ASTRIDE 36
#define BSTRIDE 136

__global__ __launch_bounds__(256, 2) void gemm_tf32_bias(
    const float* __restrict__ A, const float* __restrict__ B,
    const float* __restrict__ bias, float* __restrict__ C,
    int M, int N, int K)
{
    __shared__ unsigned As[128 * ASTRIDE];   // [m][k], 18.0 KB
    __shared__ unsigned Bs[32 * BSTRIDE];    // [k][n], 17.0 KB

    const int tid  = threadIdx.x;
    const int lane = tid & 31;
    const int warp = tid >> 5;
    const int wm   = warp >> 2;      // 0..1
    const int wn   = warp & 3;       // 0..3
    const int g    = lane >> 2;      // 0..7
    const int t    = lane & 3;       // 0..3

    const int bn = blockIdx.x;       // N tile
    const int bm = blockIdx.y;       // M tile

    const float* Ab = A + (size_t)bm * 128 * K;
    const float* Bb = B + (size_t)bn * 128;

    float acc[4][4][4];
    #pragma unroll
    for (int i = 0; i < 4; i++)
        #pragma unroll
        for (int j = 0; j < 4; j++)
            #pragma unroll
            for (int r = 0; r < 4; r++) acc[i][j][r] = 0.f;

    for (int kt = 0; kt < K; kt += 32) {
        // --- stage A tile: 128x32, 1024 float4 loads over 256 threads (4 ea)
        #pragma unroll
        for (int it = 0; it < 4; it++) {
            int idx = tid + it * 256;           // 0..1023
            int m   = idx >> 3;                 // 0..127
            int k4  = (idx & 7) * 4;            // 0..28
            float4 v = *(const float4*)(Ab + (size_t)m * K + kt + k4);
            unsigned* dst = &As[m * ASTRIDE + k4];
            uint4 w;
            w.x = f2tf32(v.x); w.y = f2tf32(v.y);
            w.z = f2tf32(v.z); w.w = f2tf32(v.w);
            *(uint4*)dst = w;
        }
        // --- stage B tile: 32x128
        #pragma unroll
        for (int it = 0; it < 4; it++) {
            int idx = tid + it * 256;
            int k   = idx >> 5;                 // 0..31
            int n4  = (idx & 31) * 4;           // 0..124
            float4 v = *(const float4*)(Bb + (size_t)(kt + k) * N + n4);
            unsigned* dst = &Bs[k * BSTRIDE + n4];
            uint4 w;
            w.x = f2tf32(v.x); w.y = f2tf32(v.y);
            w.z = f2tf32(v.z); w.w = f2tf32(v.w);
            *(uint4*)dst = w;
        }
        __syncthreads();

        #pragma unroll
        for (int ks = 0; ks < 4; ks++) {
            const int k0 = ks * 8;
            unsigned af[4][4];
            #pragma unroll
            for (int i = 0; i < 4; i++) {
                int r = wm * 64 + i * 16;
                af[i][0] = As[(r + g)     * ASTRIDE + k0 + t];
                af[i][1] = As[(r + g + 8) * ASTRIDE + k0 + t];
                af[i][2] = As[(r + g)     * ASTRIDE + k0 + t + 4];
                af[i][3] = As[(r + g + 8) * ASTRIDE + k0 + t + 4];
            }
            unsigned bf[4][2];
            #pragma unroll
            for (int j = 0; j < 4; j++) {
                int c = wn * 32 + j * 8 + g;
                bf[j][0] = Bs[(k0 + t)     * BSTRIDE + c];
                bf[j][1] = Bs[(k0 + t + 4) * BSTRIDE + c];
            }
            #pragma unroll
            for (int i = 0; i < 4; i++)
                #pragma unroll
                for (int j = 0; j < 4; j++) {
                    asm volatile(
                        "mma.sync.aligned.m16n8k8.row.col.f32.tf32.tf32.f32 "
                        "{%0,%1,%2,%3}, {%4,%5,%6,%7}, {%8,%9}, {%0,%1,%2,%3};"
                        : "+f"(acc[i][j][0]), "+f"(acc[i][j][1]),
                          "+f"(acc[i][j][2]), "+f"(acc[i][j][3])
                        : "r"(af[i][0]), "r"(af[i][1]), "r"(af[i][2]), "r"(af[i][3]),
                          "r"(bf[j][0]), "r"(bf[j][1]));
                }
        }
        __syncthreads();
    }

    // epilogue: c0,c1 at (g, 2t), (g, 2t+1); c2,c3 at (g+8, ...)
    #pragma unroll
    for (int i = 0; i < 4; i++) {
        int row0 = bm * 128 + wm * 64 + i * 16 + g;
        #pragma unroll
        for (int j = 0; j < 4; j++) {
            int col = bn * 128 + wn * 32 + j * 8 + t * 2;
            float b0 = bias[col], b1 = bias[col + 1];
            float2 v0 = make_float2(acc[i][j][0] + b0, acc[i][j][1] + b1);
            float2 v1 = make_float2(acc[i][j][2] + b0, acc[i][j][3] + b1);
            *(float2*)(C + (size_t)row0 * N + col)       = v0;
            *(float2*)(C + (size_t)(row0 + 8) * N + col) = v1;
        }
    }
}

// ---------------------------------------------------------------------------
// Fused attention: one block per (head, window). 256 threads = 8 warps.
// ---------------------------------------------------------------------------
#define KSTRIDE 65

__global__ __launch_bounds__(256) void attn_kernel(
    const float* __restrict__ q, const float* __restrict__ kv,
    const int* __restrict__ mask_l,
    const int* __restrict__ mask_r,
    const int* __restrict__ nW_ptr,
    const float* __restrict__ rel_table,
    const float* __restrict__ cls_self,
    const float* __restrict__ cls_up,
    const float* __restrict__ cls_down,
    float* __restrict__ ao)
{
    const int h = blockIdx.x;
    const int b = blockIdx.y;
    const int tid = threadIdx.x;
    const int lane = tid & 31;
    const int warp = tid >> 5;

    extern __shared__ float sm[];
    float* Ks = sm;                         // [129][65]
    float* Vs = Ks + MTOK * KSTRIDE;        // [129][65]
    float* Qs = Vs + MTOK * KSTRIDE;        // [65][64]
    float* Ps = Qs + NTOK * HDIM;           // [8][132]

    const int nW = *nW_ptr;
    const int mc = (nW < 2) ? nW : 2;
    const int w = b % nW;
    const bool use_l = (w < mc);
    const bool use_r = (w >= nW - mc);
    const int* ml = mask_l + (size_t)w * NTOK * MTOK;
    const int* mr = mask_r +
        (size_t)(2 - mc + (w - (nW - mc))) * NTOK * MTOK;

    const float* kvb = kv + (size_t)b * MTOK * 2 * CDIM + h * HDIM;
    for (int idx = tid; idx < MTOK * HDIM; idx += 256) {
        int m = idx >> 6, d = idx & 63;
        Ks[m * KSTRIDE + d] = kvb[(size_t)m * 2048 + d];
        Vs[m * KSTRIDE + d] = kvb[(size_t)m * 2048 + CDIM + d];
    }
    const float* qb = q + (size_t)b * NTOK * CDIM + h * HDIM;
    for (int idx = tid; idx < NTOK * HDIM; idx += 256) {
        Qs[idx] = qb[(size_t)(idx >> 6) * CDIM + (idx & 63)];
    }
    __syncthreads();

    const float scale = 0.125f;
    const float NEG = -3.402823466e38f;

    for (int n = warp; n < NTOK; n += 8) {
        const int nm = (lane == 0) ? 5 : 4;
        float s[5];

        for (int j = 0; j < nm; j++) {
            const int m = lane + 32 * j;
            const float* kr = Ks + m * KSTRIDE;
            const float* qr = Qs + n * HDIM;
            float acc = 0.f;
            #pragma unroll
            for (int d = 0; d < HDIM; d++) acc = fmaf(qr[d], kr[d], acc);
            acc *= scale;

            float bias;
            if (n == 0)
                bias = (m == 0) ? cls_self[h] : cls_up[h * (MTOK - 1) + (m - 1)];
            else
                bias = (m == 0) ? cls_down[h * (NTOK - 1) + (n - 1)]
                                : rel_table[(n - m + 127) * NHEAD + h];
            acc += bias;

            bool masked = false;
            if (use_l) masked = ml[n * MTOK + m] != 0;
            if (use_r) masked = masked || (mr[n * MTOK + m] != 0);
            s[j] = masked ? NEG : acc;
        }

        float mx = s[0];
        for (int j = 1; j < nm; j++) mx = fmaxf(mx, s[j]);
        #pragma unroll
        for (int o = 16; o; o >>= 1) mx = fmaxf(mx, __shfl_xor_sync(0xffffffffu, mx, o));
        float sum = 0.f, p[5];
        for (int j = 0; j < nm; j++) { p[j] = __expf(s[j] - mx); sum += p[j]; }
        #pragma unroll
        for (int o = 16; o; o >>= 1) sum += __shfl_xor_sync(0xffffffffu, sum, o);
        const float inv = 1.f / sum;

        float* Prow = Ps + warp * 132;
        for (int j = 0; j < nm; j++) Prow[lane + 32 * j] = p[j] * inv;
        __syncwarp();

        float o0 = 0.f, o1 = 0.f;
        for (int m = 0; m < MTOK; m++) {
            const float pm = Prow[m];
            o0 = fmaf(pm, Vs[m * KSTRIDE + lane], o0);
            o1 = fmaf(pm, Vs[m * KSTRIDE + lane + 32], o1);
        }
        float* aor = ao + ((size_t)b * NTOK + n) * CDIM + h * HDIM;
        aor[lane]      = o0;
        aor[lane + 32] = o1;
        __syncwarp();
    }
}

// ---------------------------------------------------------------------------
extern "C" void kernel_launch(void* const* d_in, const int* in_sizes, int n_in,
                              void* d_out, int out_size)
{
    const float* x        = (const float*)d_in[0];
    const float* x_       = (const float*)d_in[1];
    const int*   mask_l   = (const int*)d_in[2];
    const int*   mask_r   = (const int*)d_in[3];
    const int*   nW_ptr   = (const int*)d_in[4];
    const float* Wq       = (const float*)d_in[5];
    const float* bq       = (const float*)d_in[6];
    const float* Wkv      = (const float*)d_in[7];
    const float* bkv      = (const float*)d_in[8];
    const float* Wp       = (const float*)d_in[9];
    const float* bp       = (const float*)d_in[10];
    const float* rel      = (const float*)d_in[11];
    const float* cls_self = (const float*)d_in[12];
    const float* cls_up   = (const float*)d_in[13];
    const float* cls_down = (const float*)d_in[14];

    const int BnW = in_sizes[0] / (NTOK * CDIM);   // 512
    const int Mq  = BnW * NTOK;                    // 33280
    const int Mkv = BnW * MTOK;                    // 66048

    float *qbuf, *kvbuf, *aobuf;
    cudaGetSymbolAddress((void**)&qbuf,  g_q);
    cudaGetSymbolAddress((void**)&kvbuf, g_kv);
    cudaGetSymbolAddress((void**)&aobuf, g_ao);

    gemm_tf32_bias<<<dim3(CDIM / 128, Mq / 128), 256>>>(x, Wq, bq, qbuf, Mq, CDIM, CDIM);
    gemm_tf32_bias<<<dim3(2 * CDIM / 128, Mkv / 128), 256>>>(x_, Wkv, bkv, kvbuf, Mkv, 2 * CDIM, CDIM);

    const int smem_bytes = (MTOK * KSTRIDE * 2 + NTOK * HDIM + 8 * 132) * sizeof(float);
    cudaFuncSetAttribute(attn_kernel, cudaFuncAttributeMaxDynamicSharedMemorySize, smem_bytes);
    attn_kernel<<<dim3(NHEAD, BnW), 256, smem_bytes>>>(
        qbuf, kvbuf, mask_l, mask_r, nW_ptr, rel, cls_self, cls_up, cls_down, aobuf);

    gemm_tf32_bias<<<dim3(CDIM / 128, Mq / 128), 256>>>(aobuf, Wp, bp, (float*)d_out, Mq, CDIM, CDIM);
}

// round 4
// speedup vs baseline: 2.6080x; 1.1150x over previous
#include <cuda_runtime.h>
#include <cuda_bf16.h>

#define NTOK 65
#define MTOK 129
#define NHEAD 16
#define HDIM 64
#define CDIM 1024

// fp32 intermediates
__device__ float g_q [512 * NTOK * CDIM];
__device__ float g_kv[512 * MTOK * 2 * CDIM];
__device__ float g_ao[512 * NTOK * CDIM];       // written tf32-rounded by attention
// tf32-rounded GEMM inputs
__device__ float g_xc  [512 * NTOK * CDIM];
__device__ float g_x_c [512 * MTOK * CDIM];
__device__ float g_wqc [CDIM * CDIM];
__device__ float g_wkvc[CDIM * 2 * CDIM];
__device__ float g_wpc [CDIM * CDIM];

__device__ __forceinline__ unsigned f2tf32(float x) {
    unsigned r;
    asm("cvt.rna.tf32.f32 %0, %1;" : "=r"(r) : "f"(x));
    return r;
}

// elementwise fp32 -> tf32(round-nearest) bit pattern, float4 vectorized
__global__ __launch_bounds__(256) void cvt_tf32(
    const float4* __restrict__ in, float4* __restrict__ out, int n4)
{
    int i = blockIdx.x * blockDim.x + threadIdx.x;
    if (i < n4) {
        float4 v = in[i];
        uint4 w;
        w.x = f2tf32(v.x); w.y = f2tf32(v.y);
        w.z = f2tf32(v.z); w.w = f2tf32(v.w);
        out[i] = *(float4*)&w;
    }
}

__device__ __forceinline__ void cp16(float* s, const float* g) {
    unsigned sa = (unsigned)__cvta_generic_to_shared(s);
    asm volatile("cp.async.cg.shared.global [%0], [%1], 16;\n"
                 :: "r"(sa), "l"(g) : "memory");
}

// ---------------------------------------------------------------------------
// tf32 tensor-core GEMM, cp.async 2-stage pipeline.
// C[M,N] = A[M,K] @ B[K,N] + bias[N]; A,B already tf32-rounded.
// 128x128x32 tile, 256 threads = 8 warps (2Mx4N), warp tile 64x32.
// ---------------------------------------------------------------------------
#define ASTRIDE 36
#define BSTRIDE 136
#define A_TILE (128 * ASTRIDE)
#define B_TILE (32 * BSTRIDE)

__global__ __launch_bounds__(256, 2) void gemm_tf32_bias(
    const float* __restrict__ A, const float* __restrict__ B,
    const float* __restrict__ bias, float* __restrict__ C,
    int M, int N, int K)
{
    extern __shared__ float smg[];
    float* As = smg;                // [2][A_TILE]
    float* Bs = smg + 2 * A_TILE;   // [2][B_TILE]

    const int tid  = threadIdx.x;
    const int lane = tid & 31;
    const int warp = tid >> 5;
    const int wm   = warp >> 2;
    const int wn   = warp & 3;
    const int g    = lane >> 2;
    const int t    = lane & 3;

    const int bn = blockIdx.x;
    const int bm = blockIdx.y;
    const float* Ab = A + (size_t)bm * 128 * K;
    const float* Bb = B + (size_t)bn * 128;

    float acc[4][4][4];
    #pragma unroll
    for (int i = 0; i < 4; i++)
        #pragma unroll
        for (int j = 0; j < 4; j++)
            #pragma unroll
            for (int r = 0; r < 4; r++) acc[i][j][r] = 0.f;

    // stage issue: A 128x32 (1024 16B chunks), B 32x128 (1024 chunks)
    auto issue = [&](int kt, int buf) {
        #pragma unroll
        for (int it = 0; it < 4; it++) {
            int idx = tid + it * 256;
            int m = idx >> 3, c = (idx & 7) * 4;
            cp16(As + buf * A_TILE + m * ASTRIDE + c,
                 Ab + (size_t)m * K + kt + c);
        }
        #pragma unroll
        for (int it = 0; it < 4; it++) {
            int idx = tid + it * 256;
            int k = idx >> 5, n4 = (idx & 31) * 4;
            cp16(Bs + buf * B_TILE + k * BSTRIDE + n4,
                 Bb + (size_t)(kt + k) * N + n4);
        }
        asm volatile("cp.async.commit_group;\n" ::: "memory");
    };

    issue(0, 0);
    const int NT = K >> 5;
    for (int ti = 0; ti < NT; ti++) {
        const int cur = ti & 1;
        if (ti + 1 < NT) {
            issue((ti + 1) << 5, cur ^ 1);
            asm volatile("cp.async.wait_group 1;\n" ::: "memory");
        } else {
            asm volatile("cp.async.wait_group 0;\n" ::: "memory");
        }
        __syncthreads();

        const unsigned* Asc = (const unsigned*)(As + cur * A_TILE);
        const unsigned* Bsc = (const unsigned*)(Bs + cur * B_TILE);

        #pragma unroll
        for (int ks = 0; ks < 4; ks++) {
            const int k0 = ks * 8;
            unsigned af[4][4];
            #pragma unroll
            for (int i = 0; i < 4; i++) {
                int r = wm * 64 + i * 16;
                af[i][0] = Asc[(r + g)     * ASTRIDE + k0 + t];
                af[i][1] = Asc[(r + g + 8) * ASTRIDE + k0 + t];
                af[i][2] = Asc[(r + g)     * ASTRIDE + k0 + t + 4];
                af[i][3] = Asc[(r + g + 8) * ASTRIDE + k0 + t + 4];
            }
            unsigned bf[4][2];
            #pragma unroll
            for (int j = 0; j < 4; j++) {
                int c = wn * 32 + j * 8 + g;
                bf[j][0] = Bsc[(k0 + t)     * BSTRIDE + c];
                bf[j][1] = Bsc[(k0 + t + 4) * BSTRIDE + c];
            }
            #pragma unroll
            for (int i = 0; i < 4; i++)
                #pragma unroll
                for (int j = 0; j < 4; j++) {
                    asm volatile(
                        "mma.sync.aligned.m16n8k8.row.col.f32.tf32.tf32.f32 "
                        "{%0,%1,%2,%3}, {%4,%5,%6,%7}, {%8,%9}, {%0,%1,%2,%3};"
                        : "+f"(acc[i][j][0]), "+f"(acc[i][j][1]),
                          "+f"(acc[i][j][2]), "+f"(acc[i][j][3])
                        : "r"(af[i][0]), "r"(af[i][1]), "r"(af[i][2]), "r"(af[i][3]),
                          "r"(bf[j][0]), "r"(bf[j][1]));
                }
        }
        __syncthreads();
    }

    #pragma unroll
    for (int i = 0; i < 4; i++) {
        int row0 = bm * 128 + wm * 64 + i * 16 + g;
        #pragma unroll
        for (int j = 0; j < 4; j++) {
            int col = bn * 128 + wn * 32 + j * 8 + t * 2;
            float b0 = bias[col], b1 = bias[col + 1];
            float2 v0 = make_float2(acc[i][j][0] + b0, acc[i][j][1] + b1);
            float2 v1 = make_float2(acc[i][j][2] + b0, acc[i][j][3] + b1);
            *(float2*)(C + (size_t)row0 * N + col)       = v0;
            *(float2*)(C + (size_t)(row0 + 8) * N + col) = v1;
        }
    }
}

// ---------------------------------------------------------------------------
// Fused attention v2: float4 LDS, 2-row n-blocking, transposed V, smem bias.
// One block per (head, window), 256 threads = 8 warps.
// ---------------------------------------------------------------------------
#define KSTR 68
#define VSTR 132
#define PSTR 132

__global__ __launch_bounds__(256) void attn_kernel(
    const float* __restrict__ q, const float* __restrict__ kv,
    const int* __restrict__ mask_l,
    const int* __restrict__ mask_r,
    const int* __restrict__ nW_ptr,
    const float* __restrict__ rel_table,
    const float* __restrict__ cls_self,
    const float* __restrict__ cls_up,
    const float* __restrict__ cls_down,
    float* __restrict__ ao)
{
    const int h = blockIdx.x;
    const int b = blockIdx.y;
    const int tid = threadIdx.x;
    const int lane = tid & 31;
    const int warp = tid >> 5;

    extern __shared__ float sm[];
    float* Ks = sm;                          // [129][68]
    float* Vt = Ks + MTOK * KSTR;            // [64][132] transposed
    float* Qs = Vt + HDIM * VSTR;            // [65][64]
    float* Ps = Qs + NTOK * HDIM;            // [8][2][132]
    float* tb = Ps + 8 * 2 * PSTR;           // rel 0..190, self 191, up 192.., down 320..

    // bias tables
    for (int i = tid; i < 191; i += 256) tb[i] = rel_table[i * NHEAD + h];
    if (tid == 0) tb[191] = cls_self[h];
    for (int i = tid; i < 128; i += 256) tb[192 + i] = cls_up[h * (MTOK - 1) + i];
    for (int i = tid; i < 64; i += 256) tb[320 + i] = cls_down[h * (NTOK - 1) + i];

    // stage K (row-major, stride 68) and V transposed
    const float* kvb = kv + (size_t)b * MTOK * 2 * CDIM + h * HDIM;
    for (int idx = tid; idx < MTOK * 16; idx += 256) {
        int m = idx >> 4, d4 = (idx & 15) << 2;
        float4 kk = *(const float4*)(kvb + (size_t)m * 2048 + d4);
        *(float4*)(Ks + m * KSTR + d4) = kk;
        float4 vv = *(const float4*)(kvb + (size_t)m * 2048 + CDIM + d4);
        Vt[(d4 + 0) * VSTR + m] = vv.x;
        Vt[(d4 + 1) * VSTR + m] = vv.y;
        Vt[(d4 + 2) * VSTR + m] = vv.z;
        Vt[(d4 + 3) * VSTR + m] = vv.w;
    }
    const float* qb = q + (size_t)b * NTOK * CDIM + h * HDIM;
    for (int idx = tid; idx < NTOK * 16; idx += 256) {
        int n = idx >> 4, d4 = (idx & 15) << 2;
        *(float4*)(Qs + n * HDIM + d4) = *(const float4*)(qb + (size_t)n * CDIM + d4);
    }
    __syncthreads();

    const int nW = *nW_ptr;
    const int mc = (nW < 2) ? nW : 2;
    const int w = b % nW;
    const bool use_l = (w < mc);
    const bool use_r = (w >= nW - mc);
    const int* ml = mask_l + (size_t)w * NTOK * MTOK;
    const int* mr = mask_r + (size_t)(2 - mc + (w - (nW - mc))) * NTOK * MTOK;

    const float scale = 0.125f;
    const float NEG = -3.402823466e38f;

    for (int n0 = warp * 2; n0 < NTOK; n0 += 16) {
        const bool two = (n0 + 1 < NTOK);
        const int n1 = two ? n0 + 1 : n0;
        const int nm = (lane == 0) ? 5 : 4;
        float s0[5], s1[5];
        const float4* q0 = (const float4*)(Qs + n0 * HDIM);
        const float4* q1 = (const float4*)(Qs + n1 * HDIM);

        for (int j = 0; j < nm; j++) {
            const int m = lane + 32 * j;
            const float4* kr = (const float4*)(Ks + m * KSTR);
            float a0 = 0.f, a1 = 0.f;
            #pragma unroll
            for (int d4 = 0; d4 < 16; d4++) {
                float4 kvv = kr[d4];
                float4 qa = q0[d4];
                float4 qc = q1[d4];
                a0 = fmaf(kvv.x, qa.x, fmaf(kvv.y, qa.y,
                     fmaf(kvv.z, qa.z, fmaf(kvv.w, qa.w, a0))));
                a1 = fmaf(kvv.x, qc.x, fmaf(kvv.y, qc.y,
                     fmaf(kvv.z, qc.z, fmaf(kvv.w, qc.w, a1))));
            }
            a0 *= scale; a1 *= scale;

            // bias from smem tables
            float bias0 = (n0 == 0)
                ? ((m == 0) ? tb[191] : tb[192 + m - 1])
                : ((m == 0) ? tb[320 + n0 - 1] : tb[n0 - m + 127]);
            float bias1 = (n1 == 0)
                ? ((m == 0) ? tb[191] : tb[192 + m - 1])
                : ((m == 0) ? tb[320 + n1 - 1] : tb[n1 - m + 127]);
            a0 += bias0; a1 += bias1;

            bool m0 = false, m1 = false;
            if (use_l) { m0 = ml[n0 * MTOK + m] != 0; m1 = ml[n1 * MTOK + m] != 0; }
            if (use_r) { m0 = m0 || (mr[n0 * MTOK + m] != 0);
                         m1 = m1 || (mr[n1 * MTOK + m] != 0); }
            s0[j] = m0 ? NEG : a0;
            s1[j] = m1 ? NEG : a1;
        }

        // softmax (two rows)
        float* Prow0 = Ps + warp * 2 * PSTR;
        float* Prow1 = Prow0 + PSTR;
        {
            float mx = s0[0];
            for (int j = 1; j < nm; j++) mx = fmaxf(mx, s0[j]);
            #pragma unroll
            for (int o = 16; o; o >>= 1) mx = fmaxf(mx, __shfl_xor_sync(~0u, mx, o));
            float sum = 0.f, p[5];
            for (int j = 0; j < nm; j++) { p[j] = __expf(s0[j] - mx); sum += p[j]; }
            #pragma unroll
            for (int o = 16; o; o >>= 1) sum += __shfl_xor_sync(~0u, sum, o);
            float inv = 1.f / sum;
            for (int j = 0; j < nm; j++) Prow0[lane + 32 * j] = p[j] * inv;
        }
        {
            float mx = s1[0];
            for (int j = 1; j < nm; j++) mx = fmaxf(mx, s1[j]);
            #pragma unroll
            for (int o = 16; o; o >>= 1) mx = fmaxf(mx, __shfl_xor_sync(~0u, mx, o));
            float sum = 0.f, p[5];
            for (int j = 0; j < nm; j++) { p[j] = __expf(s1[j] - mx); sum += p[j]; }
            #pragma unroll
            for (int o = 16; o; o >>= 1) sum += __shfl_xor_sync(~0u, sum, o);
            float inv = 1.f / sum;
            for (int j = 0; j < nm; j++) Prow1[lane + 32 * j] = p[j] * inv;
        }
        __syncwarp();

        // PV: V read as float4 over m (transposed layout), shared across rows
        float o00 = 0.f, o01 = 0.f, o10 = 0.f, o11 = 0.f;
        const float4* v0 = (const float4*)(Vt + lane * VSTR);
        const float4* v1 = (const float4*)(Vt + (lane + 32) * VSTR);
        const float4* p0 = (const float4*)Prow0;
        const float4* p1 = (const float4*)Prow1;
        #pragma unroll
        for (int m4 = 0; m4 < 32; m4++) {
            float4 va = v0[m4], vb = v1[m4];
            float4 pa = p0[m4], pb = p1[m4];
            o00 = fmaf(pa.x, va.x, fmaf(pa.y, va.y, fmaf(pa.z, va.z, fmaf(pa.w, va.w, o00))));
            o01 = fmaf(pa.x, vb.x, fmaf(pa.y, vb.y, fmaf(pa.z, vb.z, fmaf(pa.w, vb.w, o01))));
            o10 = fmaf(pb.x, va.x, fmaf(pb.y, va.y, fmaf(pb.z, va.z, fmaf(pb.w, va.w, o10))));
            o11 = fmaf(pb.x, vb.x, fmaf(pb.y, vb.y, fmaf(pb.z, vb.z, fmaf(pb.w, vb.w, o11))));
        }
        {   // tail m = 128
            float pt0 = Prow0[128], pt1 = Prow1[128];
            float va = Vt[lane * VSTR + 128], vb = Vt[(lane + 32) * VSTR + 128];
            o00 = fmaf(pt0, va, o00); o01 = fmaf(pt0, vb, o01);
            o10 = fmaf(pt1, va, o10); o11 = fmaf(pt1, vb, o11);
        }

        float* aor0 = ao + ((size_t)b * NTOK + n0) * CDIM + h * HDIM;
        aor0[lane]      = __uint_as_float(f2tf32(o00));
        aor0[lane + 32] = __uint_as_float(f2tf32(o01));
        if (two) {
            float* aor1 = ao + ((size_t)b * NTOK + n1) * CDIM + h * HDIM;
            aor1[lane]      = __uint_as_float(f2tf32(o10));
            aor1[lane + 32] = __uint_as_float(f2tf32(o11));
        }
        __syncwarp();
    }
}

// ---------------------------------------------------------------------------
extern "C" void kernel_launch(void* const* d_in, const int* in_sizes, int n_in,
                              void* d_out, int out_size)
{
    const float* x        = (const float*)d_in[0];
    const float* x_       = (const float*)d_in[1];
    const int*   mask_l   = (const int*)d_in[2];
    const int*   mask_r   = (const int*)d_in[3];
    const int*   nW_ptr   = (const int*)d_in[4];
    const float* Wq       = (const float*)d_in[5];
    const float* bq       = (const float*)d_in[6];
    const float* Wkv      = (const float*)d_in[7];
    const float* bkv      = (const float*)d_in[8];
    const float* Wp       = (const float*)d_in[9];
    const float* bp       = (const float*)d_in[10];
    const float* rel      = (const float*)d_in[11];
    const float* cls_self = (const float*)d_in[12];
    const float* cls_up   = (const float*)d_in[13];
    const float* cls_down = (const float*)d_in[14];

    const int BnW = in_sizes[0] / (NTOK * CDIM);   // 512
    const int Mq  = BnW * NTOK;                    // 33280
    const int Mkv = BnW * MTOK;                    // 66048

    float *qbuf, *kvbuf, *aobuf, *xc, *x_c, *wqc, *wkvc, *wpc;
    cudaGetSymbolAddress((void**)&qbuf,  g_q);
    cudaGetSymbolAddress((void**)&kvbuf, g_kv);
    cudaGetSymbolAddress((void**)&aobuf, g_ao);
    cudaGetSymbolAddress((void**)&xc,    g_xc);
    cudaGetSymbolAddress((void**)&x_c,   g_x_c);
    cudaGetSymbolAddress((void**)&wqc,   g_wqc);
    cudaGetSymbolAddress((void**)&wkvc,  g_wkvc);
    cudaGetSymbolAddress((void**)&wpc,   g_wpc);

    // pre-convert GEMM inputs to tf32 bit patterns
    auto cvt = [&](const float* src, float* dst, long long n) {
        int n4 = (int)(n / 4);
        cvt_tf32<<<(n4 + 255) / 256, 256>>>((const float4*)src, (float4*)dst, n4);
    };
    cvt(x,   xc,   (long long)Mq * CDIM);
    cvt(x_,  x_c,  (long long)Mkv * CDIM);
    cvt(Wq,  wqc,  (long long)CDIM * CDIM);
    cvt(Wkv, wkvc, (long long)CDIM * 2 * CDIM);
    cvt(Wp,  wpc,  (long long)CDIM * CDIM);

    const int gemm_smem = (2 * A_TILE + 2 * B_TILE) * sizeof(float);   // 71680
    cudaFuncSetAttribute(gemm_tf32_bias, cudaFuncAttributeMaxDynamicSharedMemorySize, gemm_smem);

    gemm_tf32_bias<<<dim3(CDIM / 128, Mq / 128), 256, gemm_smem>>>(
        xc, wqc, bq, qbuf, Mq, CDIM, CDIM);
    gemm_tf32_bias<<<dim3(2 * CDIM / 128, Mkv / 128), 256, gemm_smem>>>(
        x_c, wkvc, bkv, kvbuf, Mkv, 2 * CDIM, CDIM);

    const int attn_smem = (MTOK * KSTR + HDIM * VSTR + NTOK * HDIM
                           + 8 * 2 * PSTR + 392) * sizeof(float);
    cudaFuncSetAttribute(attn_kernel, cudaFuncAttributeMaxDynamicSharedMemorySize, attn_smem);
    attn_kernel<<<dim3(NHEAD, BnW), 256, attn_smem>>>(
        qbuf, kvbuf, mask_l, mask_r, nW_ptr, rel, cls_self, cls_up, cls_down, aobuf);

    gemm_tf32_bias<<<dim3(CDIM / 128, Mq / 128), 256, gemm_smem>>>(
        aobuf, wpc, bp, (float*)d_out, Mq, CDIM, CDIM);
}

// round 6
// speedup vs baseline: 2.6922x; 1.0323x over previous
#include <cuda_runtime.h>
#include <cuda_bf16.h>
#include <cstdint>

#define NTOK 65
#define MTOK 129
#define NHEAD 16
#define HDIM 64
#define CDIM 1024

// fp32 intermediates
__device__ float g_q [512 * NTOK * CDIM];
__device__ float g_kv[512 * MTOK * 2 * CDIM];
__device__ float g_ao[512 * NTOK * CDIM];     // tf32-rounded + k-permuted by attention
// tf32-rounded, k-permuted GEMM inputs
__device__ float g_xc  [512 * NTOK * CDIM];
__device__ float g_x_c [512 * MTOK * CDIM];
__device__ float g_wqt [CDIM * CDIM];         // [N][K] k-permuted
__device__ float g_wkvt[2 * CDIM * CDIM];
__device__ float g_wpt [CDIM * CDIM];

__device__ __forceinline__ unsigned f2tf32(float x) {
    unsigned r;
    asm("cvt.rna.tf32.f32 %0, %1;" : "=r"(r) : "f"(x));
    return r;
}
__device__ __forceinline__ void cp16s(uint32_t s, const float* g) {
    asm volatile("cp.async.cg.shared.global [%0], [%1], 16;"
                 :: "r"(s), "l"(g) : "memory");
}
__device__ __forceinline__ uint32_t smem_u32(const void* p) {
    uint32_t a;
    asm("{ .reg .u64 t; cvta.to.shared.u64 t, %1; cvt.u32.u64 %0, t; }"
        : "=r"(a) : "l"(p));
    return a;
}

// k-permutation within 8-groups: dest p(k) = (k&~7)|((k&3)<<1)|((k>>2)&1)
// so that fragment pairs (t, t+4) are adjacent words.

// ---------------------------------------------------------------------------
// prepass: fp32 -> tf32-rounded, k-permuted. 8 elements per thread.
// ---------------------------------------------------------------------------
__global__ __launch_bounds__(256) void cvt_tf32_perm(
    const float4* __restrict__ in, float4* __restrict__ out, int n8)
{
    int i = blockIdx.x * blockDim.x + threadIdx.x;
    if (i < n8) {
        float4 a = in[2 * i], b = in[2 * i + 1];
        uint4 o0, o1;
        o0.x = f2tf32(a.x); o0.y = f2tf32(b.x);
        o0.z = f2tf32(a.y); o0.w = f2tf32(b.y);
        o1.x = f2tf32(a.z); o1.y = f2tf32(b.z);
        o1.z = f2tf32(a.w); o1.w = f2tf32(b.w);
        out[2 * i]     = *(float4*)&o0;
        out[2 * i + 1] = *(float4*)&o1;
    }
}

// W[K][N] fp32 -> Wt[N][perm(K)] tf32-rounded
__global__ __launch_bounds__(256) void transpose_tf32_perm(
    const float* __restrict__ W, float* __restrict__ Wt, int K, int N)
{
    __shared__ float t[32][33];
    const int n0 = blockIdx.x * 32, k0 = blockIdx.y * 32;
    const int tx = threadIdx.x & 31, ty = threadIdx.x >> 5;   // 32x8
    #pragma unroll
    for (int i = 0; i < 4; i++)
        t[ty + 8 * i][tx] = W[(size_t)(k0 + ty + 8 * i) * N + n0 + tx];
    __syncthreads();
    const int pk = (tx & ~7) | ((tx & 3) << 1) | ((tx >> 2) & 1);
    #pragma unroll
    for (int i = 0; i < 4; i++)
        Wt[(size_t)(n0 + ty + 8 * i) * K + k0 + pk] =
            __uint_as_float(f2tf32(t[tx][ty + 8 * i]));
}

// ---------------------------------------------------------------------------
// tf32 mma.sync GEMM with k-permuted operands, both staged [row][k].
// C[M,N] = A[M,K] @ Bt[N,K]^T + bias[N]
// 128x128x32 block tile, 8 warps (2Mx4N), warp tile 64x32, 2-stage cp.async.
// Smem row stride 40 words -> LDS.64 fragment loads are conflict-free.
// ---------------------------------------------------------------------------
#define GS 40
#define TILE_W (128 * GS)              // words per operand per stage
#define STAGE_W (2 * TILE_W)           // A + B

__global__ __launch_bounds__(256, 2) void gemm_mma(
    const float* __restrict__ A, const float* __restrict__ Bt,
    const float* __restrict__ bias, float* __restrict__ C,
    int M, int N, int K)
{
    extern __shared__ float smg[];     // [2][STAGE_W] = 81920 B

    const int tid  = threadIdx.x;
    const int lane = tid & 31;
    const int warp = tid >> 5;
    const int wm   = warp >> 2;        // 0..1
    const int wn   = warp & 3;         // 0..3
    const int g    = lane >> 2;        // 0..7
    const int t    = lane & 3;         // 0..3

    const int bn = blockIdx.x, bm = blockIdx.y;
    const float* Ag = A  + (size_t)bm * 128 * K;
    const float* Bg = Bt + (size_t)bn * 128 * K;
    const uint32_t sb = smem_u32(smg);

    float acc[4][4][4];
    #pragma unroll
    for (int i = 0; i < 4; i++)
        #pragma unroll
        for (int j = 0; j < 4; j++)
            #pragma unroll
            for (int r = 0; r < 4; r++) acc[i][j][r] = 0.f;

    // stage: A 128 rows x 8 chunks + B 128 rows x 8 chunks = 2048 cp16
    auto issue = [&](int kt, int s) {
        const uint32_t base = sb + s * (STAGE_W * 4);
        #pragma unroll
        for (int it = 0; it < 8; it++) {
            int idx = tid + it * 256;
            int row = (idx >> 3) & 127, c = idx & 7;
            if (idx < 1024)
                cp16s(base + (row * GS + c * 4) * 4,
                      Ag + (size_t)row * K + kt + c * 4);
            else
                cp16s(base + (TILE_W + row * GS + c * 4) * 4,
                      Bg + (size_t)row * K + kt + c * 4);
        }
        asm volatile("cp.async.commit_group;" ::: "memory");
    };

    issue(0, 0);
    const int NT = K >> 5;
    for (int ti = 0; ti < NT; ti++) {
        const int cur = ti & 1;
        if (ti + 1 < NT) {
            issue((ti + 1) << 5, cur ^ 1);
            asm volatile("cp.async.wait_group 1;" ::: "memory");
        } else {
            asm volatile("cp.async.wait_group 0;" ::: "memory");
        }
        __syncthreads();

        const float* As = smg + cur * STAGE_W;
        const float* Bs = As + TILE_W;

        #pragma unroll
        for (int ks = 0; ks < 4; ks++) {
            const int k0 = ks * 8 + 2 * t;
            unsigned af[4][4];
            #pragma unroll
            for (int i = 0; i < 4; i++) {
                int r = wm * 64 + i * 16 + g;
                uint2 lo = *(const uint2*)(As + r * GS + k0);        // (t, t+4)
                uint2 hi = *(const uint2*)(As + (r + 8) * GS + k0);
                af[i][0] = lo.x; af[i][2] = lo.y;
                af[i][1] = hi.x; af[i][3] = hi.y;
            }
            unsigned bf[4][2];
            #pragma unroll
            for (int j = 0; j < 4; j++) {
                int n = wn * 32 + j * 8 + g;
                uint2 bb = *(const uint2*)(Bs + n * GS + k0);
                bf[j][0] = bb.x; bf[j][1] = bb.y;
            }
            #pragma unroll
            for (int i = 0; i < 4; i++)
                #pragma unroll
                for (int j = 0; j < 4; j++) {
                    asm volatile(
                        "mma.sync.aligned.m16n8k8.row.col.f32.tf32.tf32.f32 "
                        "{%0,%1,%2,%3}, {%4,%5,%6,%7}, {%8,%9}, {%0,%1,%2,%3};"
                        : "+f"(acc[i][j][0]), "+f"(acc[i][j][1]),
                          "+f"(acc[i][j][2]), "+f"(acc[i][j][3])
                        : "r"(af[i][0]), "r"(af[i][1]), "r"(af[i][2]), "r"(af[i][3]),
                          "r"(bf[j][0]), "r"(bf[j][1]));
                }
        }
        __syncthreads();
    }

    #pragma unroll
    for (int i = 0; i < 4; i++) {
        int row0 = bm * 128 + wm * 64 + i * 16 + g;
        #pragma unroll
        for (int j = 0; j < 4; j++) {
            int col = bn * 128 + wn * 32 + j * 8 + t * 2;
            float b0 = bias[col], b1 = bias[col + 1];
            float2 v0 = make_float2(acc[i][j][0] + b0, acc[i][j][1] + b1);
            float2 v1 = make_float2(acc[i][j][2] + b0, acc[i][j][3] + b1);
            *(float2*)(C + (size_t)row0 * N + col)       = v0;
            *(float2*)(C + (size_t)(row0 + 8) * N + col) = v1;
        }
    }
}

// ---------------------------------------------------------------------------
// Fused attention (R4 core; output written tf32-rounded AND k-permuted)
// ---------------------------------------------------------------------------
#define KSTR 68
#define VSTR 132
#define PSTR 132

__global__ __launch_bounds__(256) void attn_kernel(
    const float* __restrict__ q, const float* __restrict__ kv,
    const int* __restrict__ mask_l,
    const int* __restrict__ mask_r,
    const int* __restrict__ nW_ptr,
    const float* __restrict__ rel_table,
    const float* __restrict__ cls_self,
    const float* __restrict__ cls_up,
    const float* __restrict__ cls_down,
    float* __restrict__ ao)
{
    const int h = blockIdx.x;
    const int b = blockIdx.y;
    const int tid = threadIdx.x;
    const int lane = tid & 31;
    const int warp = tid >> 5;

    extern __shared__ float sm[];
    float* Ks = sm;
    float* Vt = Ks + MTOK * KSTR;
    float* Qs = Vt + HDIM * VSTR;
    float* Ps = Qs + NTOK * HDIM;
    float* tb = Ps + 8 * 2 * PSTR;

    for (int i = tid; i < 191; i += 256) tb[i] = rel_table[i * NHEAD + h];
    if (tid == 0) tb[191] = cls_self[h];
    for (int i = tid; i < 128; i += 256) tb[192 + i] = cls_up[h * (MTOK - 1) + i];
    for (int i = tid; i < 64; i += 256) tb[320 + i] = cls_down[h * (NTOK - 1) + i];

    const float* kvb = kv + (size_t)b * MTOK * 2 * CDIM + h * HDIM;
    for (int idx = tid; idx < MTOK * 16; idx += 256) {
        int m = idx >> 4, d4 = (idx & 15) << 2;
        float4 kk = *(const float4*)(kvb + (size_t)m * 2048 + d4);
        *(float4*)(Ks + m * KSTR + d4) = kk;
        float4 vv = *(const float4*)(kvb + (size_t)m * 2048 + CDIM + d4);
        Vt[(d4 + 0) * VSTR + m] = vv.x;
        Vt[(d4 + 1) * VSTR + m] = vv.y;
        Vt[(d4 + 2) * VSTR + m] = vv.z;
        Vt[(d4 + 3) * VSTR + m] = vv.w;
    }
    const float* qb = q + (size_t)b * NTOK * CDIM + h * HDIM;
    for (int idx = tid; idx < NTOK * 16; idx += 256) {
        int n = idx >> 4, d4 = (idx & 15) << 2;
        *(float4*)(Qs + n * HDIM + d4) = *(const float4*)(qb + (size_t)n * CDIM + d4);
    }
    __syncthreads();

    const int nW = *nW_ptr;
    const int mc = (nW < 2) ? nW : 2;
    const int w = b % nW;
    const bool use_l = (w < mc);
    const bool use_r = (w >= nW - mc);
    const int* ml = mask_l + (size_t)w * NTOK * MTOK;
    const int* mr = mask_r + (size_t)(2 - mc + (w - (nW - mc))) * NTOK * MTOK;

    const float scale = 0.125f;
    const float NEG = -3.402823466e38f;

    // permuted output channel indices for this lane
    const int d0 = lane, d1 = lane + 32;
    const int pd0 = (d0 & ~7) | ((d0 & 3) << 1) | ((d0 >> 2) & 1);
    const int pd1 = (d1 & ~7) | ((d1 & 3) << 1) | ((d1 >> 2) & 1);

    for (int n0 = warp * 2; n0 < NTOK; n0 += 16) {
        const bool two = (n0 + 1 < NTOK);
        const int n1 = two ? n0 + 1 : n0;
        const int nm = (lane == 0) ? 5 : 4;
        float s0[5], s1[5];
        const float4* q0 = (const float4*)(Qs + n0 * HDIM);
        const float4* q1 = (const float4*)(Qs + n1 * HDIM);

        for (int j = 0; j < nm; j++) {
            const int m = lane + 32 * j;
            const float4* kr = (const float4*)(Ks + m * KSTR);
            float a0 = 0.f, a1 = 0.f;
            #pragma unroll
            for (int d4 = 0; d4 < 16; d4++) {
                float4 kvv = kr[d4];
                float4 qa = q0[d4];
                float4 qc = q1[d4];
                a0 = fmaf(kvv.x, qa.x, fmaf(kvv.y, qa.y,
                     fmaf(kvv.z, qa.z, fmaf(kvv.w, qa.w, a0))));
                a1 = fmaf(kvv.x, qc.x, fmaf(kvv.y, qc.y,
                     fmaf(kvv.z, qc.z, fmaf(kvv.w, qc.w, a1))));
            }
            a0 *= scale; a1 *= scale;

            float bias0 = (n0 == 0)
                ? ((m == 0) ? tb[191] : tb[192 + m - 1])
                : ((m == 0) ? tb[320 + n0 - 1] : tb[n0 - m + 127]);
            float bias1 = (n1 == 0)
                ? ((m == 0) ? tb[191] : tb[192 + m - 1])
                : ((m == 0) ? tb[320 + n1 - 1] : tb[n1 - m + 127]);
            a0 += bias0; a1 += bias1;

            bool m0 = false, m1 = false;
            if (use_l) { m0 = ml[n0 * MTOK + m] != 0; m1 = ml[n1 * MTOK + m] != 0; }
            if (use_r) { m0 = m0 || (mr[n0 * MTOK + m] != 0);
                         m1 = m1 || (mr[n1 * MTOK + m] != 0); }
            s0[j] = m0 ? NEG : a0;
            s1[j] = m1 ? NEG : a1;
        }

        float* Prow0 = Ps + warp * 2 * PSTR;
        float* Prow1 = Prow0 + PSTR;
        {
            float mx = s0[0];
            for (int j = 1; j < nm; j++) mx = fmaxf(mx, s0[j]);
            #pragma unroll
            for (int o = 16; o; o >>= 1) mx = fmaxf(mx, __shfl_xor_sync(~0u, mx, o));
            float sum = 0.f, p[5];
            for (int j = 0; j < nm; j++) { p[j] = __expf(s0[j] - mx); sum += p[j]; }
            #pragma unroll
            for (int o = 16; o; o >>= 1) sum += __shfl_xor_sync(~0u, sum, o);
            float inv = 1.f / sum;
            for (int j = 0; j < nm; j++) Prow0[lane + 32 * j] = p[j] * inv;
        }
        {
            float mx = s1[0];
            for (int j = 1; j < nm; j++) mx = fmaxf(mx, s1[j]);
            #pragma unroll
            for (int o = 16; o; o >>= 1) mx = fmaxf(mx, __shfl_xor_sync(~0u, mx, o));
            float sum = 0.f, p[5];
            for (int j = 0; j < nm; j++) { p[j] = __expf(s1[j] - mx); sum += p[j]; }
            #pragma unroll
            for (int o = 16; o; o >>= 1) sum += __shfl_xor_sync(~0u, sum, o);
            float inv = 1.f / sum;
            for (int j = 0; j < nm; j++) Prow1[lane + 32 * j] = p[j] * inv;
        }
        __syncwarp();

        float o00 = 0.f, o01 = 0.f, o10 = 0.f, o11 = 0.f;
        const float4* v0 = (const float4*)(Vt + lane * VSTR);
        const float4* v1 = (const float4*)(Vt + (lane + 32) * VSTR);
        const float4* p0 = (const float4*)Prow0;
        const float4* p1 = (const float4*)Prow1;
        #pragma unroll
        for (int m4 = 0; m4 < 32; m4++) {
            float4 va = v0[m4], vb = v1[m4];
            float4 pa = p0[m4], pb = p1[m4];
            o00 = fmaf(pa.x, va.x, fmaf(pa.y, va.y, fmaf(pa.z, va.z, fmaf(pa.w, va.w, o00))));
            o01 = fmaf(pa.x, vb.x, fmaf(pa.y, vb.y, fmaf(pa.z, vb.z, fmaf(pa.w, vb.w, o01))));
            o10 = fmaf(pb.x, va.x, fmaf(pb.y, va.y, fmaf(pb.z, va.z, fmaf(pb.w, va.w, o10))));
            o11 = fmaf(pb.x, vb.x, fmaf(pb.y, vb.y, fmaf(pb.z, vb.z, fmaf(pb.w, vb.w, o11))));
        }
        {
            float pt0 = Prow0[128], pt1 = Prow1[128];
            float va = Vt[lane * VSTR + 128], vb = Vt[(lane + 32) * VSTR + 128];
            o00 = fmaf(pt0, va, o00); o01 = fmaf(pt0, vb, o01);
            o10 = fmaf(pt1, va, o10); o11 = fmaf(pt1, vb, o11);
        }

        float* aor0 = ao + ((size_t)b * NTOK + n0) * CDIM + h * HDIM;
        aor0[pd0] = __uint_as_float(f2tf32(o00));
        aor0[pd1] = __uint_as_float(f2tf32(o01));
        if (two) {
            float* aor1 = ao + ((size_t)b * NTOK + n1) * CDIM + h * HDIM;
            aor1[pd0] = __uint_as_float(f2tf32(o10));
            aor1[pd1] = __uint_as_float(f2tf32(o11));
        }
        __syncwarp();
    }
}

// ---------------------------------------------------------------------------
extern "C" void kernel_launch(void* const* d_in, const int* in_sizes, int n_in,
                              void* d_out, int out_size)
{
    const float* x        = (const float*)d_in[0];
    const float* x_       = (const float*)d_in[1];
    const int*   mask_l   = (const int*)d_in[2];
    const int*   mask_r   = (const int*)d_in[3];
    const int*   nW_ptr   = (const int*)d_in[4];
    const float* Wq       = (const float*)d_in[5];
    const float* bq       = (const float*)d_in[6];
    const float* Wkv      = (const float*)d_in[7];
    const float* bkv      = (const float*)d_in[8];
    const float* Wp       = (const float*)d_in[9];
    const float* bp       = (const float*)d_in[10];
    const float* rel      = (const float*)d_in[11];
    const float* cls_self = (const float*)d_in[12];
    const float* cls_up   = (const float*)d_in[13];
    const float* cls_down = (const float*)d_in[14];

    const int BnW = in_sizes[0] / (NTOK * CDIM);   // 512
    const int Mq  = BnW * NTOK;                    // 33280
    const int Mkv = BnW * MTOK;                    // 66048

    float *qbuf, *kvbuf, *aobuf, *xc, *x_c, *wqt, *wkvt, *wpt;
    cudaGetSymbolAddress((void**)&qbuf,  g_q);
    cudaGetSymbolAddress((void**)&kvbuf, g_kv);
    cudaGetSymbolAddress((void**)&aobuf, g_ao);
    cudaGetSymbolAddress((void**)&xc,    g_xc);
    cudaGetSymbolAddress((void**)&x_c,   g_x_c);
    cudaGetSymbolAddress((void**)&wqt,   g_wqt);
    cudaGetSymbolAddress((void**)&wkvt,  g_wkvt);
    cudaGetSymbolAddress((void**)&wpt,   g_wpt);

    // activations -> tf32-rounded + k-permuted
    auto cvt = [&](const float* src, float* dst, long long n) {
        int n8 = (int)(n / 8);
        cvt_tf32_perm<<<(n8 + 255) / 256, 256>>>((const float4*)src, (float4*)dst, n8);
    };
    cvt(x,  xc,  (long long)Mq * CDIM);
    cvt(x_, x_c, (long long)Mkv * CDIM);
    // weights -> [N][perm(K)] tf32-rounded
    transpose_tf32_perm<<<dim3(CDIM / 32, CDIM / 32), 256>>>(Wq, wqt, CDIM, CDIM);
    transpose_tf32_perm<<<dim3(2 * CDIM / 32, CDIM / 32), 256>>>(Wkv, wkvt, CDIM, 2 * CDIM);
    transpose_tf32_perm<<<dim3(CDIM / 32, CDIM / 32), 256>>>(Wp, wpt, CDIM, CDIM);

    const int gsm = 2 * STAGE_W * sizeof(float);   // 81920
    cudaFuncSetAttribute(gemm_mma, cudaFuncAttributeMaxDynamicSharedMemorySize, gsm);

    gemm_mma<<<dim3(CDIM / 128, Mq / 128), 256, gsm>>>(xc, wqt, bq, qbuf, Mq, CDIM, CDIM);
    gemm_mma<<<dim3(2 * CDIM / 128, Mkv / 128), 256, gsm>>>(x_c, wkvt, bkv, kvbuf, Mkv, 2 * CDIM, CDIM);

    const int attn_smem = (MTOK * KSTR + HDIM * VSTR + NTOK * HDIM
                           + 8 * 2 * PSTR + 392) * sizeof(float);
    cudaFuncSetAttribute(attn_kernel, cudaFuncAttributeMaxDynamicSharedMemorySize, attn_smem);
    attn_kernel<<<dim3(NHEAD, BnW), 256, attn_smem>>>(
        qbuf, kvbuf, mask_l, mask_r, nW_ptr, rel, cls_self, cls_up, cls_down, aobuf);

    gemm_mma<<<dim3(CDIM / 128, Mq / 128), 256, gsm>>>(aobuf, wpt, bp, (float*)d_out, Mq, CDIM, CDIM);
}